// round 5
// baseline (speedup 1.0000x reference)
#include <cuda_runtime.h>
#include <math.h>

#define B_    4
#define C_    128
#define N_    8192
#define CQK_  32
#define TN    64
#define TM    64

// -------- device scratch (allocation-free rule: __device__ globals) --------
__device__ float g_q  [B_ * CQK_ * N_];   // (B, 32, N)
__device__ float g_k  [B_ * CQK_ * N_];   // (B, 32, N)
__device__ float g_vt [B_ * N_   * C_];   // (B, N, 128)  V transposed
__device__ float g_pos[B_ * 3    * N_];   // (B, 3, N)    normalized xyz

// ===========================================================================
// Projection kernel: q = Wq x + bq, k = Wk x + bk, v = Wv x + bv (transposed),
// plus xyz normalization. One CTA handles 32 points of one batch.
// ===========================================================================
__global__ __launch_bounds__(256) void proj_kernel(
    const float* __restrict__ x,  const float* __restrict__ xyz,
    const float* __restrict__ Wq, const float* __restrict__ bq,
    const float* __restrict__ Wk, const float* __restrict__ bk,
    const float* __restrict__ Wv, const float* __restrict__ bv)
{
    __shared__ float xs [32][132];   // x tile, [point][channel], padded
    __shared__ float stg[32][129];   // V transpose staging

    const int b  = blockIdx.y;
    const int n0 = blockIdx.x * 32;
    const int t  = threadIdx.x;

    const float* xb = x + b * C_ * N_;
    // load x[:, n0:n0+32] tile (coalesced over n)
    for (int idx = t; idx < C_ * 32; idx += 256) {
        int c = idx >> 5, j = idx & 31;
        xs[j][c] = xb[c * N_ + n0 + j];
    }
    // normalized xyz
    if (t < 32) {
        const float* p = xyz + (b * N_ + n0 + t) * 3;
        float px = p[0], py = p[1], pz = p[2];
        float inv = 1.0f / (sqrtf(px*px + py*py + pz*pz) + 1e-8f);
        g_pos[(b*3 + 0) * N_ + n0 + t] = px * inv;
        g_pos[(b*3 + 1) * N_ + n0 + t] = py * inv;
        g_pos[(b*3 + 2) * N_ + n0 + t] = pz * inv;
    }
    __syncthreads();

    const int j = t & 31;    // point within tile
    const int g = t >> 5;    // output group (warp id)

    // ---- pass 1: q (o<32) and k (o in 32..63), 8 outputs per thread ----
    {
        float acc[8] = {0.f,0.f,0.f,0.f,0.f,0.f,0.f,0.f};
        #pragma unroll 4
        for (int cc = 0; cc < 32; cc++) {
            float4 xv = *reinterpret_cast<const float4*>(&xs[j][cc * 4]);
            #pragma unroll
            for (int i = 0; i < 8; i++) {
                int o = g * 8 + i;
                const float* Wrow = (o < 32) ? (Wq + o * C_) : (Wk + (o - 32) * C_);
                float4 w = *reinterpret_cast<const float4*>(Wrow + cc * 4);
                acc[i] = fmaf(w.x, xv.x, fmaf(w.y, xv.y,
                         fmaf(w.z, xv.z, fmaf(w.w, xv.w, acc[i]))));
            }
        }
        #pragma unroll
        for (int i = 0; i < 8; i++) {
            int o = g * 8 + i;
            if (o < 32) g_q[(b * CQK_ +  o      ) * N_ + n0 + j] = acc[i] + bq[o];
            else        g_k[(b * CQK_ + (o - 32)) * N_ + n0 + j] = acc[i] + bk[o - 32];
        }
    }

    // ---- pass 2: v, 16 channels per thread, store transposed via smem ----
    {
        float acc[16];
        #pragma unroll
        for (int i = 0; i < 16; i++) acc[i] = 0.f;
        #pragma unroll 2
        for (int cc = 0; cc < 32; cc++) {
            float4 xv = *reinterpret_cast<const float4*>(&xs[j][cc * 4]);
            #pragma unroll
            for (int i = 0; i < 16; i++) {
                const float* Wrow = Wv + (g * 16 + i) * C_;
                float4 w = *reinterpret_cast<const float4*>(Wrow + cc * 4);
                acc[i] = fmaf(w.x, xv.x, fmaf(w.y, xv.y,
                         fmaf(w.z, xv.z, fmaf(w.w, xv.w, acc[i]))));
            }
        }
        #pragma unroll
        for (int i = 0; i < 16; i++)
            stg[j][g * 16 + i] = acc[i] + bv[g * 16 + i];
        __syncthreads();
        // coalesced transposed store: g_vt[b][n][c]
        for (int idx = t; idx < 32 * C_; idx += 256) {
            int jj = idx >> 7, c = idx & 127;
            g_vt[(b * N_ + n0 + jj) * C_ + c] = stg[jj][c];
        }
    }
}

// ===========================================================================
// Fused flash-attention kernel. One CTA = 64 queries of one batch.
// smem floats: qs 64*33 | ks 64*33 | vs 64*132 | S 64*65 | pq 3*64 | pk 3*64
//              | Mrow 64 | Lrow 64 | rsc 64   == 17408 floats (69632 B)
// ===========================================================================
#define SMEM_FLOATS (TN*33 + TM*33 + TM*132 + TN*65 + 3*TN + 3*TM + 3*TN)

__global__ __launch_bounds__(256, 2) void attn_kernel(
    const float* __restrict__ x, const float* __restrict__ gamma,
    float* __restrict__ out)
{
    extern __shared__ float sm[];
    float* qs   = sm;                 // [64][33]
    float* ks   = qs + TN * 33;      // [64][33]
    float* vs   = ks + TM * 33;      // [64][132]
    float* S    = vs + TM * 132;     // [64][65]  scores -> probs -> out staging
    float* pq   = S  + TN * 65;      // [3][64]
    float* pk   = pq + 3 * TN;       // [3][64]
    float* Mrow = pk + 3 * TM;       // [64]
    float* Lrow = Mrow + TN;         // [64]
    float* rsc  = Lrow + TN;         // [64]

    const int b  = blockIdx.y;
    const int n0 = blockIdx.x * TN;
    const int t  = threadIdx.x;
    const int w  = t >> 5, l = t & 31;
    const int tx = t & 15, ty = t >> 4;

    // load Q tile (coalesced over n)
    const float* qb = g_q + b * CQK_ * N_;
    for (int idx = t; idx < TN * CQK_; idx += 256) {
        int c = idx >> 6, r = idx & 63;
        qs[r * 33 + c] = qb[c * N_ + n0 + r];
    }
    if (t < TN) {
        pq[0*TN + t] = g_pos[(b*3 + 0) * N_ + n0 + t];
        pq[1*TN + t] = g_pos[(b*3 + 1) * N_ + n0 + t];
        pq[2*TN + t] = g_pos[(b*3 + 2) * N_ + n0 + t];
        Mrow[t] = -1e30f;
        Lrow[t] = 0.f;
    }

    float acc[8][4];
    #pragma unroll
    for (int i = 0; i < 8; i++)
        #pragma unroll
        for (int e = 0; e < 4; e++) acc[i][e] = 0.f;

    const float* kb = g_k + b * CQK_ * N_;

    for (int m0 = 0; m0 < N_; m0 += TM) {
        __syncthreads();   // previous iteration's consumers done with ks/vs/S

        // load K tile
        for (int idx = t; idx < TM * CQK_; idx += 256) {
            int c = idx >> 6, r = idx & 63;
            ks[r * 33 + c] = kb[c * N_ + m0 + r];
        }
        // load V tile (transposed source -> conflict-free float4 STS)
        for (int idx = t; idx < TM * 32; idx += 256) {
            int m = idx >> 5, c4 = (idx & 31) << 2;
            float4 v = *reinterpret_cast<const float4*>(
                &g_vt[(b * N_ + m0 + m) * C_ + c4]);
            *reinterpret_cast<float4*>(&vs[m * 132 + c4]) = v;
        }
        if (t < TM) {
            pk[0*TM + t] = g_pos[(b*3 + 0) * N_ + m0 + t];
            pk[1*TM + t] = g_pos[(b*3 + 1) * N_ + m0 + t];
            pk[2*TM + t] = g_pos[(b*3 + 2) * N_ + m0 + t];
        }
        __syncthreads();

        // ---- phase A: S = Q K^T + 0.1 * pos_corr (4x4 register block) ----
        float s[4][4];
        #pragma unroll
        for (int i = 0; i < 4; i++)
            #pragma unroll
            for (int jj = 0; jj < 4; jj++) s[i][jj] = 0.f;

        #pragma unroll 4
        for (int c = 0; c < CQK_; c++) {
            float a[4], bb[4];
            #pragma unroll
            for (int i = 0; i < 4; i++)  a[i]  = qs[(4*ty + i) * 33 + c];
            #pragma unroll
            for (int jj = 0; jj < 4; jj++) bb[jj] = ks[(4*tx + jj) * 33 + c];
            #pragma unroll
            for (int i = 0; i < 4; i++)
                #pragma unroll
                for (int jj = 0; jj < 4; jj++)
                    s[i][jj] = fmaf(a[i], bb[jj], s[i][jj]);
        }
        #pragma unroll
        for (int i = 0; i < 4; i++) {
            float px = pq[0*TN + 4*ty + i];
            float py = pq[1*TN + 4*ty + i];
            float pz = pq[2*TN + 4*ty + i];
            #pragma unroll
            for (int jj = 0; jj < 4; jj++) {
                float d = px * pk[0*TM + 4*tx + jj]
                        + py * pk[1*TM + 4*tx + jj]
                        + pz * pk[2*TM + 4*tx + jj];
                s[i][jj] += 0.1f * d;
            }
        }
        #pragma unroll
        for (int i = 0; i < 4; i++)
            #pragma unroll
            for (int jj = 0; jj < 4; jj++)
                S[(4*ty + i) * 65 + 4*tx + jj] = s[i][jj];
        __syncthreads();

        // ---- row stats + exp (online softmax) ----
        if (t < TN) {
            int r = t;
            float old = Mrow[r];
            float mx  = old;
            #pragma unroll 8
            for (int jj = 0; jj < TM; jj++) mx = fmaxf(mx, S[r * 65 + jj]);
            float rs  = __expf(old - mx);
            float sum = 0.f;
            #pragma unroll 8
            for (int jj = 0; jj < TM; jj++) {
                float p = __expf(S[r * 65 + jj] - mx);
                S[r * 65 + jj] = p;
                sum += p;
            }
            Lrow[r] = Lrow[r] * rs + sum;
            Mrow[r] = mx;
            rsc[r]  = rs;
        }
        __syncthreads();

        // ---- rescale accumulators ----
        #pragma unroll
        for (int qi = 0; qi < 8; qi++) {
            float rr = rsc[w * 8 + qi];
            acc[qi][0] *= rr; acc[qi][1] *= rr;
            acc[qi][2] *= rr; acc[qi][3] *= rr;
        }

        // ---- phase B: acc += P * V (float4 V, broadcast P) ----
        #pragma unroll 2
        for (int m = 0; m < TM; m++) {
            float4 v4 = *reinterpret_cast<const float4*>(&vs[m * 132 + 4 * l]);
            #pragma unroll
            for (int qi = 0; qi < 8; qi++) {
                float p = S[(w * 8 + qi) * 65 + m];
                acc[qi][0] = fmaf(p, v4.x, acc[qi][0]);
                acc[qi][1] = fmaf(p, v4.y, acc[qi][1]);
                acc[qi][2] = fmaf(p, v4.z, acc[qi][2]);
                acc[qi][3] = fmaf(p, v4.w, acc[qi][3]);
            }
        }
    }

    // ---- epilogue: out = gamma * acc / L + x, transposed store via smem ----
    float gm = gamma[0];
    float fac[8];
    #pragma unroll
    for (int qi = 0; qi < 8; qi++) fac[qi] = gm / Lrow[w * 8 + qi];

    const float* xb = x + b * C_ * N_;
    #pragma unroll
    for (int cg = 0; cg < 2; cg++) {
        __syncthreads();   // S free to reuse as staging
        if ((l >> 4) == cg) {
            #pragma unroll
            for (int qi = 0; qi < 8; qi++)
                #pragma unroll
                for (int e = 0; e < 4; e++)
                    S[(w * 8 + qi) * 65 + (4 * l + e - cg * 64)] = acc[qi][e] * fac[qi];
        }
        __syncthreads();
        for (int idx = t; idx < 64 * 64; idx += 256) {
            int cl = idx >> 6, nl = idx & 63;
            int c  = cg * 64 + cl;
            out[(b * C_ + c) * N_ + n0 + nl] =
                S[nl * 65 + cl] + xb[c * N_ + n0 + nl];
        }
    }
}

// ===========================================================================
extern "C" void kernel_launch(void* const* d_in, const int* in_sizes, int n_in,
                              void* d_out, int out_size)
{
    (void)in_sizes; (void)n_in; (void)out_size;
    const float* x     = (const float*)d_in[0];
    const float* xyz   = (const float*)d_in[1];
    const float* Wq    = (const float*)d_in[2];
    const float* bq    = (const float*)d_in[3];
    const float* Wk    = (const float*)d_in[4];
    const float* bk    = (const float*)d_in[5];
    const float* Wv    = (const float*)d_in[6];
    const float* bv    = (const float*)d_in[7];
    const float* gamma = (const float*)d_in[8];
    float* out = (float*)d_out;

    // opt-in to >48KB dynamic smem (idempotent, not a stream op — capture-safe)
    cudaFuncSetAttribute(attn_kernel,
                         cudaFuncAttributeMaxDynamicSharedMemorySize,
                         SMEM_FLOATS * (int)sizeof(float));

    dim3 pg(N_ / 32, B_);
    proj_kernel<<<pg, 256>>>(x, xyz, Wq, bq, Wk, bk, Wv, bv);

    dim3 ag(N_ / TN, B_);
    attn_kernel<<<ag, 256, SMEM_FLOATS * sizeof(float)>>>(x, gamma, out);
}

// round 6
// speedup vs baseline: 1.0008x; 1.0008x over previous
#include <cuda_runtime.h>
#include <math.h>

#define B_    4
#define C_    128
#define N_    8192
#define CQK_  32
#define TN    64
#define TM    64

// -------- device scratch (allocation-free rule: __device__ globals) --------
__device__ float g_q  [B_ * CQK_ * N_];   // (B, 32, N)
__device__ float g_k  [B_ * CQK_ * N_];   // (B, 32, N)
__device__ float g_vt [B_ * N_   * C_];   // (B, N, 128)  V transposed
__device__ float g_pos[B_ * 3    * N_];   // (B, 3, N)    normalized xyz

// ===========================================================================
// Projection kernel: q = Wq x + bq, k = Wk x + bk, v = Wv x + bv (transposed),
// plus xyz normalization. One CTA handles 32 points of one batch.
// ===========================================================================
__global__ __launch_bounds__(256) void proj_kernel(
    const float* __restrict__ x,  const float* __restrict__ xyz,
    const float* __restrict__ Wq, const float* __restrict__ bq,
    const float* __restrict__ Wk, const float* __restrict__ bk,
    const float* __restrict__ Wv, const float* __restrict__ bv)
{
    __shared__ float xs [32][132];   // x tile, [point][channel], padded
    __shared__ float stg[32][129];   // V transpose staging

    const int b  = blockIdx.y;
    const int n0 = blockIdx.x * 32;
    const int t  = threadIdx.x;

    const float* xb = x + b * C_ * N_;
    // load x[:, n0:n0+32] tile (coalesced over n)
    for (int idx = t; idx < C_ * 32; idx += 256) {
        int c = idx >> 5, j = idx & 31;
        xs[j][c] = xb[c * N_ + n0 + j];
    }
    // normalized xyz
    if (t < 32) {
        const float* p = xyz + (b * N_ + n0 + t) * 3;
        float px = p[0], py = p[1], pz = p[2];
        float inv = 1.0f / (sqrtf(px*px + py*py + pz*pz) + 1e-8f);
        g_pos[(b*3 + 0) * N_ + n0 + t] = px * inv;
        g_pos[(b*3 + 1) * N_ + n0 + t] = py * inv;
        g_pos[(b*3 + 2) * N_ + n0 + t] = pz * inv;
    }
    __syncthreads();

    const int j = t & 31;    // point within tile
    const int g = t >> 5;    // output group (warp id)

    // ---- pass 1: q (o<32) and k (o in 32..63), 8 outputs per thread ----
    {
        float acc[8] = {0.f,0.f,0.f,0.f,0.f,0.f,0.f,0.f};
        #pragma unroll 4
        for (int cc = 0; cc < 32; cc++) {
            float4 xv = *reinterpret_cast<const float4*>(&xs[j][cc * 4]);
            #pragma unroll
            for (int i = 0; i < 8; i++) {
                int o = g * 8 + i;
                const float* Wrow = (o < 32) ? (Wq + o * C_) : (Wk + (o - 32) * C_);
                float4 w = *reinterpret_cast<const float4*>(Wrow + cc * 4);
                acc[i] = fmaf(w.x, xv.x, fmaf(w.y, xv.y,
                         fmaf(w.z, xv.z, fmaf(w.w, xv.w, acc[i]))));
            }
        }
        #pragma unroll
        for (int i = 0; i < 8; i++) {
            int o = g * 8 + i;
            if (o < 32) g_q[(b * CQK_ +  o      ) * N_ + n0 + j] = acc[i] + bq[o];
            else        g_k[(b * CQK_ + (o - 32)) * N_ + n0 + j] = acc[i] + bk[o - 32];
        }
    }

    // ---- pass 2: v, 16 channels per thread, store transposed via smem ----
    {
        float acc[16];
        #pragma unroll
        for (int i = 0; i < 16; i++) acc[i] = 0.f;
        #pragma unroll 2
        for (int cc = 0; cc < 32; cc++) {
            float4 xv = *reinterpret_cast<const float4*>(&xs[j][cc * 4]);
            #pragma unroll
            for (int i = 0; i < 16; i++) {
                const float* Wrow = Wv + (g * 16 + i) * C_;
                float4 w = *reinterpret_cast<const float4*>(Wrow + cc * 4);
                acc[i] = fmaf(w.x, xv.x, fmaf(w.y, xv.y,
                         fmaf(w.z, xv.z, fmaf(w.w, xv.w, acc[i]))));
            }
        }
        #pragma unroll
        for (int i = 0; i < 16; i++)
            stg[j][g * 16 + i] = acc[i] + bv[g * 16 + i];
        __syncthreads();
        // coalesced transposed store: g_vt[b][n][c]
        for (int idx = t; idx < 32 * C_; idx += 256) {
            int jj = idx >> 7, c = idx & 127;
            g_vt[(b * N_ + n0 + jj) * C_ + c] = stg[jj][c];
        }
    }
}

// ===========================================================================
// Fused flash-attention kernel. One CTA = 64 queries of one batch.
// smem floats: qs 64*33 | ks 64*33 | vs 64*132 | S 64*65 | pq 3*64 | pk 3*64
//              | Mrow 64 | Lrow 64 | rsc 64   == 17408 floats (69632 B)
// ===========================================================================
#define SMEM_FLOATS (TN*33 + TM*33 + TM*132 + TN*65 + 3*TN + 3*TM + 3*TN)

__global__ __launch_bounds__(256, 2) void attn_kernel(
    const float* __restrict__ x, const float* __restrict__ gamma,
    float* __restrict__ out)
{
    extern __shared__ float sm[];
    float* qs   = sm;                 // [64][33]
    float* ks   = qs + TN * 33;      // [64][33]
    float* vs   = ks + TM * 33;      // [64][132]
    float* S    = vs + TM * 132;     // [64][65]  scores -> probs -> out staging
    float* pq   = S  + TN * 65;      // [3][64]
    float* pk   = pq + 3 * TN;       // [3][64]
    float* Mrow = pk + 3 * TM;       // [64]
    float* Lrow = Mrow + TN;         // [64]
    float* rsc  = Lrow + TN;         // [64]

    const int b  = blockIdx.y;
    const int n0 = blockIdx.x * TN;
    const int t  = threadIdx.x;
    const int w  = t >> 5, l = t & 31;
    const int tx = t & 15, ty = t >> 4;

    // load Q tile (coalesced over n)
    const float* qb = g_q + b * CQK_ * N_;
    for (int idx = t; idx < TN * CQK_; idx += 256) {
        int c = idx >> 6, r = idx & 63;
        qs[r * 33 + c] = qb[c * N_ + n0 + r];
    }
    if (t < TN) {
        pq[0*TN + t] = g_pos[(b*3 + 0) * N_ + n0 + t];
        pq[1*TN + t] = g_pos[(b*3 + 1) * N_ + n0 + t];
        pq[2*TN + t] = g_pos[(b*3 + 2) * N_ + n0 + t];
        Mrow[t] = -1e30f;
        Lrow[t] = 0.f;
    }

    float acc[8][4];
    #pragma unroll
    for (int i = 0; i < 8; i++)
        #pragma unroll
        for (int e = 0; e < 4; e++) acc[i][e] = 0.f;

    const float* kb = g_k + b * CQK_ * N_;

    for (int m0 = 0; m0 < N_; m0 += TM) {
        __syncthreads();   // previous iteration's consumers done with ks/vs/S

        // load K tile
        for (int idx = t; idx < TM * CQK_; idx += 256) {
            int c = idx >> 6, r = idx & 63;
            ks[r * 33 + c] = kb[c * N_ + m0 + r];
        }
        // load V tile (transposed source -> conflict-free float4 STS)
        for (int idx = t; idx < TM * 32; idx += 256) {
            int m = idx >> 5, c4 = (idx & 31) << 2;
            float4 v = *reinterpret_cast<const float4*>(
                &g_vt[(b * N_ + m0 + m) * C_ + c4]);
            *reinterpret_cast<float4*>(&vs[m * 132 + c4]) = v;
        }
        if (t < TM) {
            pk[0*TM + t] = g_pos[(b*3 + 0) * N_ + m0 + t];
            pk[1*TM + t] = g_pos[(b*3 + 1) * N_ + m0 + t];
            pk[2*TM + t] = g_pos[(b*3 + 2) * N_ + m0 + t];
        }
        __syncthreads();

        // ---- phase A: S = Q K^T + 0.1 * pos_corr (4x4 register block) ----
        float s[4][4];
        #pragma unroll
        for (int i = 0; i < 4; i++)
            #pragma unroll
            for (int jj = 0; jj < 4; jj++) s[i][jj] = 0.f;

        #pragma unroll 4
        for (int c = 0; c < CQK_; c++) {
            float a[4], bb[4];
            #pragma unroll
            for (int i = 0; i < 4; i++)  a[i]  = qs[(4*ty + i) * 33 + c];
            #pragma unroll
            for (int jj = 0; jj < 4; jj++) bb[jj] = ks[(4*tx + jj) * 33 + c];
            #pragma unroll
            for (int i = 0; i < 4; i++)
                #pragma unroll
                for (int jj = 0; jj < 4; jj++)
                    s[i][jj] = fmaf(a[i], bb[jj], s[i][jj]);
        }
        #pragma unroll
        for (int i = 0; i < 4; i++) {
            float px = pq[0*TN + 4*ty + i];
            float py = pq[1*TN + 4*ty + i];
            float pz = pq[2*TN + 4*ty + i];
            #pragma unroll
            for (int jj = 0; jj < 4; jj++) {
                float d = px * pk[0*TM + 4*tx + jj]
                        + py * pk[1*TM + 4*tx + jj]
                        + pz * pk[2*TM + 4*tx + jj];
                s[i][jj] += 0.1f * d;
            }
        }
        #pragma unroll
        for (int i = 0; i < 4; i++)
            #pragma unroll
            for (int jj = 0; jj < 4; jj++)
                S[(4*ty + i) * 65 + 4*tx + jj] = s[i][jj];
        __syncthreads();

        // ---- row stats + exp (online softmax) ----
        if (t < TN) {
            int r = t;
            float old = Mrow[r];
            float mx  = old;
            #pragma unroll 8
            for (int jj = 0; jj < TM; jj++) mx = fmaxf(mx, S[r * 65 + jj]);
            float rs  = __expf(old - mx);
            float sum = 0.f;
            #pragma unroll 8
            for (int jj = 0; jj < TM; jj++) {
                float p = __expf(S[r * 65 + jj] - mx);
                S[r * 65 + jj] = p;
                sum += p;
            }
            Lrow[r] = Lrow[r] * rs + sum;
            Mrow[r] = mx;
            rsc[r]  = rs;
        }
        __syncthreads();

        // ---- rescale accumulators ----
        #pragma unroll
        for (int qi = 0; qi < 8; qi++) {
            float rr = rsc[w * 8 + qi];
            acc[qi][0] *= rr; acc[qi][1] *= rr;
            acc[qi][2] *= rr; acc[qi][3] *= rr;
        }

        // ---- phase B: acc += P * V (float4 V, broadcast P) ----
        #pragma unroll 2
        for (int m = 0; m < TM; m++) {
            float4 v4 = *reinterpret_cast<const float4*>(&vs[m * 132 + 4 * l]);
            #pragma unroll
            for (int qi = 0; qi < 8; qi++) {
                float p = S[(w * 8 + qi) * 65 + m];
                acc[qi][0] = fmaf(p, v4.x, acc[qi][0]);
                acc[qi][1] = fmaf(p, v4.y, acc[qi][1]);
                acc[qi][2] = fmaf(p, v4.z, acc[qi][2]);
                acc[qi][3] = fmaf(p, v4.w, acc[qi][3]);
            }
        }
    }

    // ---- epilogue: out = gamma * acc / L + x, transposed store via smem ----
    float gm = gamma[0];
    float fac[8];
    #pragma unroll
    for (int qi = 0; qi < 8; qi++) fac[qi] = gm / Lrow[w * 8 + qi];

    const float* xb = x + b * C_ * N_;
    #pragma unroll
    for (int cg = 0; cg < 2; cg++) {
        __syncthreads();   // S free to reuse as staging
        if ((l >> 4) == cg) {
            #pragma unroll
            for (int qi = 0; qi < 8; qi++)
                #pragma unroll
                for (int e = 0; e < 4; e++)
                    S[(w * 8 + qi) * 65 + (4 * l + e - cg * 64)] = acc[qi][e] * fac[qi];
        }
        __syncthreads();
        for (int idx = t; idx < 64 * 64; idx += 256) {
            int cl = idx >> 6, nl = idx & 63;
            int c  = cg * 64 + cl;
            out[(b * C_ + c) * N_ + n0 + nl] =
                S[nl * 65 + cl] + xb[c * N_ + n0 + nl];
        }
    }
}

// ===========================================================================
extern "C" void kernel_launch(void* const* d_in, const int* in_sizes, int n_in,
                              void* d_out, int out_size)
{
    (void)in_sizes; (void)n_in; (void)out_size;
    const float* x     = (const float*)d_in[0];
    const float* xyz   = (const float*)d_in[1];
    const float* Wq    = (const float*)d_in[2];
    const float* bq    = (const float*)d_in[3];
    const float* Wk    = (const float*)d_in[4];
    const float* bk    = (const float*)d_in[5];
    const float* Wv    = (const float*)d_in[6];
    const float* bv    = (const float*)d_in[7];
    const float* gamma = (const float*)d_in[8];
    float* out = (float*)d_out;

    // opt-in to >48KB dynamic smem (idempotent, not a stream op — capture-safe)
    cudaFuncSetAttribute(attn_kernel,
                         cudaFuncAttributeMaxDynamicSharedMemorySize,
                         SMEM_FLOATS * (int)sizeof(float));

    dim3 pg(N_ / 32, B_);
    proj_kernel<<<pg, 256>>>(x, xyz, Wq, bq, Wk, bk, Wv, bv);

    dim3 ag(N_ / TN, B_);
    attn_kernel<<<ag, 256, SMEM_FLOATS * sizeof(float)>>>(x, gamma, out);
}